// round 2
// baseline (speedup 1.0000x reference)
#include <cuda_runtime.h>

typedef unsigned int u32;
typedef unsigned long long u64;

#define HH 512
#define NS_ 376
#define NA_ 17
#define DD 393
#define TSTEPS 8
#define TM 64
#define NTHREADS 512
#define KB1 16
#define KB2 32
#define NCH2 (HH / KB2)              /* 16 */
#define WBUF_FLOATS (KB2 * HH)       /* 16384 floats = 64KB per buffer */

#define SMEM_MASK_OFF (2 * WBUF_FLOATS * 4)          /* 131072 */
#define SMEM_RED_OFF  (SMEM_MASK_OFF + HH * TM)      /* 163840 */
#define SMEM_TOTAL    (SMEM_RED_OFF + 2 * TM * 4)    /* 164352 bytes */

__device__ __forceinline__ void ffma2(u64 &d, u64 a, u64 b) {
    asm("fma.rn.f32x2 %0, %1, %2, %0;" : "+l"(d) : "l"(a), "l"(b));
}
__device__ __forceinline__ u64 splat2(float x) {
    u64 r; asm("mov.b64 %0, {%1, %1};" : "=l"(r) : "f"(x)); return r;
}
__device__ __forceinline__ float lo32(u64 v) { return __uint_as_float((u32)v); }
__device__ __forceinline__ float hi32(u64 v) { return __uint_as_float((u32)(v >> 32)); }
__device__ __forceinline__ u64 pack2(float lo, float hi) {
    return (u64)__float_as_uint(lo) | ((u64)__float_as_uint(hi) << 32);
}
__device__ __forceinline__ void cp16(u32 dst, const float* src) {
    asm volatile("cp.async.ca.shared.global [%0], [%1], 16;" :: "r"(dst), "l"(src));
}

__global__ void __launch_bounds__(NTHREADS, 1)
snn_twin_kernel(const float* __restrict__ state, const float* __restrict__ action,
                const float* __restrict__ W1a, const float* __restrict__ b1a,
                const float* __restrict__ W2a, const float* __restrict__ b2a,
                const float* __restrict__ W3a, const float* __restrict__ b3a,
                const float* __restrict__ W1b, const float* __restrict__ b1b,
                const float* __restrict__ W2b, const float* __restrict__ b2b,
                const float* __restrict__ W3b, const float* __restrict__ b3b,
                float* __restrict__ outp)
{
    extern __shared__ char smem[];
    float* Wbuf = (float*)smem;                                    // [2][KB2][HH]
    unsigned char* maskS = (unsigned char*)(smem + SMEM_MASK_OFF); // [HH][TM]
    float* Xs = (float*)(smem + SMEM_MASK_OFF);                    // [KB1][TM] (phase1 only)
    float* red = (float*)(smem + SMEM_RED_OFF);                    // [2][TM]

    const int tid = threadIdx.x;
    const int rg  = tid >> 6;   // 0..7 : rows rg*8 .. rg*8+7 of the tile
    const int ci  = tid & 63;   // 0..63: col pairs {2*ci + 128*j, +1}, j=0..3
    const int bx  = blockIdx.x;
    const int br  = bx & 1;
    const int m0  = (bx >> 1) * TM;

    const float* W1g = br ? W1b : W1a;
    const float* b1g = br ? b1b : b1a;
    const float* W2g = br ? W2b : W2a;
    const float* b2g = br ? b2b : b2a;
    const float* W3g = br ? W3b : W3a;
    const float* b3g = br ? b3b : b3a;

    u64 acc[8][4];  // phase1: h_in accumulators; phase2: v2 membrane (f32x2)
    #pragma unroll
    for (int r = 0; r < 8; ++r)
        #pragma unroll
        for (int j = 0; j < 4; ++j) acc[r][j] = 0ull;

    // ================= Phase 1: h_in = X @ W1 =================
    const int NCH1 = (DD + KB1 - 1) / KB1;  // 25
    for (int kb = 0; kb < NCH1; ++kb) {
        const int k0 = kb * KB1;
        // W1 chunk [KB1][HH] -> Wbuf (coalesced float4), zero-padded past D
        #pragma unroll
        for (int q = 0; q < 4; ++q) {
            int idx = q * 2048 + tid * 4;
            int kk = idx >> 9;
            float4 v = make_float4(0.f, 0.f, 0.f, 0.f);
            if (k0 + kk < DD)
                v = *(const float4*)(W1g + (size_t)(k0 + kk) * HH + (idx & 511));
            *(float4*)(Wbuf + idx) = v;
        }
        // X chunk transposed: Xs[kk][row]
        #pragma unroll
        for (int q = 0; q < 2; ++q) {
            int e = tid * 2 + q;
            int r = e >> 4, kk = e & 15;
            int k = k0 + kk;
            float x = 0.f;
            if (k < NS_)      x = state[(size_t)(m0 + r) * NS_ + k];
            else if (k < DD)  x = action[(size_t)(m0 + r) * NA_ + (k - NS_)];
            Xs[kk * TM + r] = x;
        }
        __syncthreads();
        const int kc = (DD - k0 < KB1) ? (DD - k0) : KB1;
        for (int kk = 0; kk < kc; ++kk) {
            const float4 xa = *(const float4*)(Xs + kk * TM + rg * 8);
            const float4 xb = *(const float4*)(Xs + kk * TM + rg * 8 + 4);
            u64 w[4];
            #pragma unroll
            for (int j = 0; j < 4; ++j)
                w[j] = *(const u64*)(Wbuf + kk * HH + 2 * ci + 128 * j);
            const float xr[8] = {xa.x, xa.y, xa.z, xa.w, xb.x, xb.y, xb.z, xb.w};
            #pragma unroll
            for (int r = 0; r < 8; ++r) {
                u64 xp = splat2(xr[r]);
                #pragma unroll
                for (int j = 0; j < 4; ++j) ffma2(acc[r][j], xp, w[j]);
            }
        }
        __syncthreads();
    }

    // ===== prefetch W2 chunk 0 -> buf 0 (overlaps with phase 1.5) =====
    const u32 wsm = (u32)__cvta_generic_to_shared(Wbuf);
    {
        #pragma unroll
        for (int q = 0; q < 8; ++q) {
            int off = q * 2048 + tid * 4;
            cp16(wsm + (u32)off * 4u, W2g + off);
        }
        asm volatile("cp.async.commit_group;");
    }

    // ===== Phase 1.5: simulate layer-1 IF -> 8-bit spike masks =====
    {
        #pragma unroll
        for (int j = 0; j < 4; ++j) {
            float2 b1j = *(const float2*)(b1g + 2 * ci + 128 * j);
            #pragma unroll
            for (int h = 0; h < 2; ++h) {
                const int c = 2 * ci + 128 * j + h;
                u64 mq = 0ull;
                #pragma unroll
                for (int r = 0; r < 8; ++r) {
                    float hv = (h ? hi32(acc[r][j]) : lo32(acc[r][j]))
                             + (h ? b1j.y : b1j.x);
                    float v = 0.f; u32 mb = 0u;
                    #pragma unroll
                    for (int t = 0; t < 8; ++t) {
                        v += hv;
                        if (v >= 1.0f) { mb |= (1u << t); v = 0.f; }
                    }
                    mq |= (u64)mb << (r * 8);
                }
                *(u64*)(maskS + (size_t)c * TM + rg * 8) = mq;
            }
        }
    }
    #pragma unroll
    for (int r = 0; r < 8; ++r)
        #pragma unroll
        for (int j = 0; j < 4; ++j) acc[r][j] = 0ull;   // acc becomes v2
    __syncthreads();

    // ============ Phase 2: 8 timesteps of V2 += S1_t @ W2 ============
    float2 b2j[4]; float w3v[8];
    #pragma unroll
    for (int j = 0; j < 4; ++j) {
        b2j[j] = *(const float2*)(b2g + 2 * ci + 128 * j);
        w3v[2 * j]     = W3g[2 * ci + 128 * j];
        w3v[2 * j + 1] = W3g[2 * ci + 128 * j + 1];
    }
    float dvrow[8];
    #pragma unroll
    for (int r = 0; r < 8; ++r) dvrow[r] = 0.f;

    int t_cur = 0;
    float cw = 0.00390625f;   // 2^-8, doubles each step -> 2^-1 at t=7
    const int gTotal = TSTEPS * NCH2;

    for (int g = 0; g < gTotal; ++g) {
        const int cb = g & (NCH2 - 1);
        // prefetch next chunk into the other buffer
        if (g + 1 < gTotal) {
            const int nb = (cb + 1) & (NCH2 - 1);
            const u32 dst = wsm + (u32)(((g + 1) & 1) * WBUF_FLOATS) * 4u;
            const float* src = W2g + (size_t)nb * KB2 * HH;
            #pragma unroll
            for (int q = 0; q < 8; ++q) {
                int off = q * 2048 + tid * 4;
                cp16(dst + (u32)off * 4u, src + off);
            }
        }
        asm volatile("cp.async.commit_group;");
        asm volatile("cp.async.wait_group 1;");
        __syncthreads();

        const float* Wb = Wbuf + (g & 1) * WBUF_FLOATS;
        const unsigned char* mp = maskS + (size_t)(cb * KB2) * TM + rg * 8;

        #pragma unroll 4
        for (int kk = 0; kk < KB2; ++kk) {
            const u64 mq = *(const u64*)(mp + (size_t)kk * TM);
            const u64 mt = mq >> t_cur;
            const u32 mlo = (u32)mt;
            const u32 mhi = (u32)(mt >> 32);
            const u64 w0 = *(const u64*)(Wb + kk * HH + 2 * ci);
            const u64 w1 = *(const u64*)(Wb + kk * HH + 2 * ci + 128);
            const u64 w2 = *(const u64*)(Wb + kk * HH + 2 * ci + 256);
            const u64 w3_ = *(const u64*)(Wb + kk * HH + 2 * ci + 384);
            #pragma unroll
            for (int r = 0; r < 8; ++r) {
                const u32 bit = (r < 4 ? mlo : mhi) & (1u << (8 * (r & 3)));
                asm volatile("{\n\t.reg .pred p;\n\tsetp.ne.u32 p, %4, 0;\n\t"
                    "@p add.rn.f32x2 %0, %0, %5;\n\t"
                    "@p add.rn.f32x2 %1, %1, %6;\n\t"
                    "@p add.rn.f32x2 %2, %2, %7;\n\t"
                    "@p add.rn.f32x2 %3, %3, %8;\n\t}"
                    : "+l"(acc[r][0]), "+l"(acc[r][1]), "+l"(acc[r][2]), "+l"(acc[r][3])
                    : "r"(bit), "l"(w0), "l"(w1), "l"(w2), "l"(w3_));
            }
        }

        if (cb == NCH2 - 1) {
            // end of timestep: add b2, threshold, reset, collect W3 term
            #pragma unroll
            for (int r = 0; r < 8; ++r) {
                #pragma unroll
                for (int j = 0; j < 4; ++j) {
                    float vl = lo32(acc[r][j]) + b2j[j].x;
                    float vh = hi32(acc[r][j]) + b2j[j].y;
                    if (vl >= 1.0f) { dvrow[r] = fmaf(cw, w3v[2*j],   dvrow[r]); vl = 0.f; }
                    if (vh >= 1.0f) { dvrow[r] = fmaf(cw, w3v[2*j+1], dvrow[r]); vh = 0.f; }
                    acc[r][j] = pack2(vl, vh);
                }
            }
            t_cur++;
            cw *= 2.0f;
        }
        __syncthreads();
    }

    // ================= Epilogue: reduce dv over the 512 cols =================
    #pragma unroll
    for (int r = 0; r < 8; ++r) {
        float v = dvrow[r];
        #pragma unroll
        for (int s = 16; s; s >>= 1) v += __shfl_xor_sync(0xffffffffu, v, s);
        if ((ci & 31) == 0) red[((ci >> 5) & 1) * TM + rg * 8 + r] = v;
    }
    __syncthreads();
    if (tid < TM) {
        float q = red[tid] + red[TM + tid] + b3g[0] * (255.0f / 256.0f);
        outp[(size_t)br * 4096 + m0 + tid] = q;
    }
    asm volatile("cp.async.wait_group 0;");
}

extern "C" void kernel_launch(void* const* d_in, const int* in_sizes, int n_in,
                              void* d_out, int out_size) {
    (void)in_sizes; (void)n_in; (void)out_size;
    cudaFuncSetAttribute(snn_twin_kernel,
                         cudaFuncAttributeMaxDynamicSharedMemorySize, SMEM_TOTAL);
    snn_twin_kernel<<<128, NTHREADS, SMEM_TOTAL>>>(
        (const float*)d_in[0], (const float*)d_in[1],
        (const float*)d_in[2], (const float*)d_in[3],
        (const float*)d_in[4], (const float*)d_in[5],
        (const float*)d_in[6], (const float*)d_in[7],
        (const float*)d_in[8], (const float*)d_in[9],
        (const float*)d_in[10], (const float*)d_in[11],
        (const float*)d_in[12], (const float*)d_in[13],
        (float*)d_out);
}

// round 4
// speedup vs baseline: 1.8277x; 1.8277x over previous
#include <cuda_runtime.h>

typedef unsigned int u32;
typedef unsigned long long u64;

#define HH 512
#define NS_ 376
#define NA_ 17
#define DD 393
#define TSTEPS 8
#define TM 64
#define NTHREADS 512
#define KB1 16
#define KB2 16
#define NCH2 (HH / KB2)              /* 32 chunks per timestep */
#define WBUF_FLOATS (KB2 * HH)       /* 8192 floats = 32KB per buffer */

#define SMEM_MASK_OFF (2 * WBUF_FLOATS * 4)          /* 65536 */
#define SMEM_SF_OFF   (SMEM_MASK_OFF + HH * TM)      /* 98304  */
#define SMEM_RED_OFF  (SMEM_SF_OFF + HH * TM * 4)    /* 229376 */
#define SMEM_TOTAL    (SMEM_RED_OFF + 2 * TM * 4)    /* 229888 bytes */

__device__ __forceinline__ void ffma2(u64 &d, u64 a, u64 b) {
    asm("fma.rn.f32x2 %0, %1, %2, %0;" : "+l"(d) : "l"(a), "l"(b));
}
__device__ __forceinline__ u64 splat2(float x) {
    u64 r; asm("mov.b64 %0, {%1, %1};" : "=l"(r) : "f"(x)); return r;
}
__device__ __forceinline__ float lo32(u64 v) { return __uint_as_float((u32)v); }
__device__ __forceinline__ float hi32(u64 v) { return __uint_as_float((u32)(v >> 32)); }
__device__ __forceinline__ u64 pack2(float lo, float hi) {
    return (u64)__float_as_uint(lo) | ((u64)__float_as_uint(hi) << 32);
}
__device__ __forceinline__ void cp16(u32 dst, const float* src) {
    asm volatile("cp.async.ca.shared.global [%0], [%1], 16;" :: "r"(dst), "l"(src));
}

__global__ void __launch_bounds__(NTHREADS, 1)
snn_twin_kernel(const float* __restrict__ state, const float* __restrict__ action,
                const float* __restrict__ W1a, const float* __restrict__ b1a,
                const float* __restrict__ W2a, const float* __restrict__ b2a,
                const float* __restrict__ W3a, const float* __restrict__ b3a,
                const float* __restrict__ W1b, const float* __restrict__ b1b,
                const float* __restrict__ W2b, const float* __restrict__ b2b,
                const float* __restrict__ W3b, const float* __restrict__ b3b,
                float* __restrict__ outp)
{
    extern __shared__ char smem[];
    float* Wbuf = (float*)smem;                                    // [2][KB2][HH]
    unsigned char* maskS = (unsigned char*)(smem + SMEM_MASK_OFF); // [HH][TM] bytes
    float* Sf = (float*)(smem + SMEM_SF_OFF);                      // [HH][TM] floats (one t)
    float* Xs = (float*)(smem + SMEM_SF_OFF);                      // [KB1][TM] (phase1 alias)
    float* red = (float*)(smem + SMEM_RED_OFF);                    // [2][TM]

    const int tid = threadIdx.x;
    const int rg  = tid >> 6;   // 0..7 : rows rg*8 .. rg*8+7
    const int ci  = tid & 63;   // 0..63: col pairs {2*ci + 128*j, +1}, j=0..3
    const int bx  = blockIdx.x;
    const int br  = bx & 1;
    const int m0  = (bx >> 1) * TM;

    const float* W1g = br ? W1b : W1a;
    const float* b1g = br ? b1b : b1a;
    const float* W2g = br ? W2b : W2a;
    const float* b2g = br ? b2b : b2a;
    const float* W3g = br ? W3b : W3a;
    const float* b3g = br ? b3b : b3a;

    u64 acc[8][4];  // phase1: h_in accumulators; phase2: v2 membrane (f32x2)
    #pragma unroll
    for (int r = 0; r < 8; ++r)
        #pragma unroll
        for (int j = 0; j < 4; ++j) acc[r][j] = 0ull;

    // ================= Phase 1: h_in = X @ W1 =================
    const int NCH1 = (DD + KB1 - 1) / KB1;  // 25
    for (int kb = 0; kb < NCH1; ++kb) {
        const int k0 = kb * KB1;
        #pragma unroll
        for (int q = 0; q < 4; ++q) {
            int idx = q * 2048 + tid * 4;
            int kk = idx >> 9;
            float4 v = make_float4(0.f, 0.f, 0.f, 0.f);
            if (k0 + kk < DD)
                v = *(const float4*)(W1g + (size_t)(k0 + kk) * HH + (idx & 511));
            *(float4*)(Wbuf + idx) = v;
        }
        #pragma unroll
        for (int q = 0; q < 2; ++q) {
            int e = tid * 2 + q;
            int r = e >> 4, kk = e & 15;
            int k = k0 + kk;
            float x = 0.f;
            if (k < NS_)      x = state[(size_t)(m0 + r) * NS_ + k];
            else if (k < DD)  x = action[(size_t)(m0 + r) * NA_ + (k - NS_)];
            Xs[kk * TM + r] = x;
        }
        __syncthreads();
        const int kc = (DD - k0 < KB1) ? (DD - k0) : KB1;
        #pragma unroll 4
        for (int kk = 0; kk < kc; ++kk) {
            const float4 xa = *(const float4*)(Xs + kk * TM + rg * 8);
            const float4 xb = *(const float4*)(Xs + kk * TM + rg * 8 + 4);
            u64 w[4];
            #pragma unroll
            for (int j = 0; j < 4; ++j)
                w[j] = *(const u64*)(Wbuf + kk * HH + 2 * ci + 128 * j);
            const float xr[8] = {xa.x, xa.y, xa.z, xa.w, xb.x, xb.y, xb.z, xb.w};
            #pragma unroll
            for (int r = 0; r < 8; ++r) {
                u64 xp = splat2(xr[r]);
                #pragma unroll
                for (int j = 0; j < 4; ++j) ffma2(acc[r][j], xp, w[j]);
            }
        }
        __syncthreads();
    }

    // ===== prefetch W2 chunk 0 -> buf 0 (overlaps phase 1.5) =====
    const u32 wsm = (u32)__cvta_generic_to_shared(Wbuf);
    {
        #pragma unroll
        for (int q = 0; q < 4; ++q) {
            int off = q * 2048 + tid * 4;
            cp16(wsm + (u32)off * 4u, W2g + off);
        }
        asm volatile("cp.async.commit_group;");
    }

    // ===== Phase 1.5: simulate layer-1 IF -> 8-bit spike masks =====
    {
        #pragma unroll
        for (int j = 0; j < 4; ++j) {
            float2 b1j = *(const float2*)(b1g + 2 * ci + 128 * j);
            #pragma unroll
            for (int h = 0; h < 2; ++h) {
                const int c = 2 * ci + 128 * j + h;
                u64 mq = 0ull;
                #pragma unroll
                for (int r = 0; r < 8; ++r) {
                    float hv = (h ? hi32(acc[r][j]) : lo32(acc[r][j]))
                             + (h ? b1j.y : b1j.x);
                    float v = 0.f; u32 mb = 0u;
                    #pragma unroll
                    for (int t = 0; t < 8; ++t) {
                        v += hv;
                        if (v >= 1.0f) { mb |= (1u << t); v = 0.f; }
                    }
                    mq |= (u64)mb << (r * 8);
                }
                *(u64*)(maskS + (size_t)c * TM + rg * 8) = mq;
            }
        }
    }
    #pragma unroll
    for (int r = 0; r < 8; ++r)
        #pragma unroll
        for (int j = 0; j < 4; ++j) acc[r][j] = 0ull;   // acc becomes v2
    __syncthreads();

    // ============ Phase 2: 8 timesteps of V2 += S1_t @ W2 ============
    float2 b2j[4]; float w3v[8];
    #pragma unroll
    for (int j = 0; j < 4; ++j) {
        b2j[j] = *(const float2*)(b2g + 2 * ci + 128 * j);
        w3v[2 * j]     = W3g[2 * ci + 128 * j];
        w3v[2 * j + 1] = W3g[2 * ci + 128 * j + 1];
    }
    float dvrow[8];
    #pragma unroll
    for (int r = 0; r < 8; ++r) dvrow[r] = 0.f;

    int t_cur = 0;
    float cw = 0.00390625f;   // 2^-8, doubles each step
    const int gTotal = TSTEPS * NCH2;   // 256

    for (int g = 0; g < gTotal; ++g) {
        const int cb = g & (NCH2 - 1);

        // issue prefetch of next chunk into the other buffer
        if (g + 1 < gTotal) {
            const int nb = (cb + 1) & (NCH2 - 1);
            const u32 dst = wsm + (u32)(((g + 1) & 1) * WBUF_FLOATS) * 4u;
            const float* src = W2g + (size_t)nb * KB2 * HH;
            #pragma unroll
            for (int q = 0; q < 4; ++q) {
                int off = q * 2048 + tid * 4;
                cp16(dst + (u32)off * 4u, src + off);
            }
        }
        asm volatile("cp.async.commit_group;");

        // start of a timestep: expand bit masks -> float spike plane Sf
        // (FULL plane: HH*TM = 32768 entries = 16 * 512thr * 4)
        if (cb == 0) {
            #pragma unroll
            for (int q = 0; q < 16; ++q) {
                const int f = q * 2048 + tid * 4;          // 4 consecutive entries
                const u32 m4 = *(const u32*)(maskS + f);   // 4 mask bytes
                float4 s;
                s.x = __uint_as_float(((m4 >>  t_cur)       & 1u) * 0x3f800000u);
                s.y = __uint_as_float(((m4 >> (t_cur + 8))  & 1u) * 0x3f800000u);
                s.z = __uint_as_float(((m4 >> (t_cur + 16)) & 1u) * 0x3f800000u);
                s.w = __uint_as_float(((m4 >> (t_cur + 24)) & 1u) * 0x3f800000u);
                *(float4*)(Sf + f) = s;
            }
        }

        asm volatile("cp.async.wait_group 1;");
        __syncthreads();

        const float* Wb = Wbuf + (g & 1) * WBUF_FLOATS;
        const float* Sp = Sf + (size_t)(cb * KB2) * TM + rg * 8;
        const int cbase = 2 * ci;

        #pragma unroll
        for (int kk = 0; kk < KB2; ++kk) {
            const float4 sa = *(const float4*)(Sp + kk * TM);
            const float4 sb = *(const float4*)(Sp + kk * TM + 4);
            const u64 w0 = *(const u64*)(Wb + kk * HH + cbase);
            const u64 w1 = *(const u64*)(Wb + kk * HH + cbase + 128);
            const u64 w2 = *(const u64*)(Wb + kk * HH + cbase + 256);
            const u64 w3_ = *(const u64*)(Wb + kk * HH + cbase + 384);
            const float sr[8] = {sa.x, sa.y, sa.z, sa.w, sb.x, sb.y, sb.z, sb.w};
            #pragma unroll
            for (int r = 0; r < 8; ++r) {
                const u64 sp = splat2(sr[r]);
                ffma2(acc[r][0], sp, w0);
                ffma2(acc[r][1], sp, w1);
                ffma2(acc[r][2], sp, w2);
                ffma2(acc[r][3], sp, w3_);
            }
        }

        if (cb == NCH2 - 1) {
            // end of timestep: add b2, threshold, reset, collect W3 term
            #pragma unroll
            for (int r = 0; r < 8; ++r) {
                #pragma unroll
                for (int j = 0; j < 4; ++j) {
                    float vl = lo32(acc[r][j]) + b2j[j].x;
                    float vh = hi32(acc[r][j]) + b2j[j].y;
                    if (vl >= 1.0f) { dvrow[r] = fmaf(cw, w3v[2*j],   dvrow[r]); vl = 0.f; }
                    if (vh >= 1.0f) { dvrow[r] = fmaf(cw, w3v[2*j+1], dvrow[r]); vh = 0.f; }
                    acc[r][j] = pack2(vl, vh);
                }
            }
            t_cur++;
            cw *= 2.0f;
        }
        __syncthreads();
    }

    // ================= Epilogue: reduce dv over the 512 cols =================
    #pragma unroll
    for (int r = 0; r < 8; ++r) {
        float v = dvrow[r];
        #pragma unroll
        for (int s = 16; s; s >>= 1) v += __shfl_xor_sync(0xffffffffu, v, s);
        if ((ci & 31) == 0) red[((ci >> 5) & 1) * TM + rg * 8 + r] = v;
    }
    __syncthreads();
    if (tid < TM) {
        float q = red[tid] + red[TM + tid] + b3g[0] * (255.0f / 256.0f);
        outp[(size_t)br * 4096 + m0 + tid] = q;
    }
    asm volatile("cp.async.wait_group 0;");
}

extern "C" void kernel_launch(void* const* d_in, const int* in_sizes, int n_in,
                              void* d_out, int out_size) {
    (void)in_sizes; (void)n_in; (void)out_size;
    cudaFuncSetAttribute(snn_twin_kernel,
                         cudaFuncAttributeMaxDynamicSharedMemorySize, SMEM_TOTAL);
    snn_twin_kernel<<<128, NTHREADS, SMEM_TOTAL>>>(
        (const float*)d_in[0], (const float*)d_in[1],
        (const float*)d_in[2], (const float*)d_in[3],
        (const float*)d_in[4], (const float*)d_in[5],
        (const float*)d_in[6], (const float*)d_in[7],
        (const float*)d_in[8], (const float*)d_in[9],
        (const float*)d_in[10], (const float*)d_in[11],
        (const float*)d_in[12], (const float*)d_in[13],
        (float*)d_out);
}